// round 4
// baseline (speedup 1.0000x reference)
#include <cuda_runtime.h>
#include <math.h>

#define NB 4096
#define IN_DIM 1024
#define HID 512
#define EMBED 128
#define NTOK 16
#define NCODES 1024
#define LATENT 2048
#define NTOKENS_TOTAL (NB * NTOK)          // 65536
#define QELEMS (NTOKENS_TOTAL * EMBED)     // 8388608
#define REC_ELEMS (NB * IN_DIM)            // 4194304

// weight pool offsets (floats)
#define OFF_EW1 0
#define OFF_EW2 524288
#define OFF_EW3 786432
#define OFF_DW1 1835008
#define OFF_DW2 2883584
#define OFF_DW3 3145728
#define OFF_CB  3670016
#define WPOOL_N 3801088

// ------------------------- scratch -------------------------
__device__ float  g_xhi[NB * IN_DIM];
__device__ float  g_xlo[NB * IN_DIM];
__device__ float  g_h1hi[NB * HID];
__device__ float  g_h1lo[NB * HID];
__device__ float  g_h2hi[NB * HID];
__device__ float  g_h2lo[NB * HID];
__device__ float  g_zhi[NB * LATENT];
__device__ float  g_zlo[NB * LATENT];
__device__ float  g_qhi[NB * LATENT];
__device__ float  g_qlo[NB * LATENT];
__device__ float  g_h3hi[NB * HID];
__device__ float  g_h3lo[NB * HID];
__device__ float  g_h4hi[NB * HID];
__device__ float  g_h4lo[NB * HID];
__device__ float  g_whi[WPOOL_N];
__device__ float  g_wlo[WPOOL_N];
__device__ float  g_cnorm[NCODES];
__device__ int    g_idx[NTOKENS_TOTAL];
__device__ double g_loss;

__device__ __forceinline__ float gelu_exact(float x) {
    return 0.5f * x * (1.0f + erff(x * 0.70710678118654752440f));
}

// ------------------------- tf32 helpers -------------------------
__device__ __forceinline__ unsigned f2tf(float x) {
    unsigned u;
    asm("cvt.rna.tf32.f32 %0, %1;" : "=r"(u) : "f"(x));
    return u;
}
__device__ __forceinline__ void mma8(float* d,
                                     unsigned a0, unsigned a1, unsigned a2, unsigned a3,
                                     unsigned b0, unsigned b1) {
    asm volatile(
        "mma.sync.aligned.m16n8k8.row.col.f32.tf32.tf32.f32 "
        "{%0,%1,%2,%3},{%4,%5,%6,%7},{%8,%9},{%0,%1,%2,%3};"
        : "+f"(d[0]), "+f"(d[1]), "+f"(d[2]), "+f"(d[3])
        : "r"(a0), "r"(a1), "r"(a2), "r"(a3), "r"(b0), "r"(b1));
}

// ------------------------- split prep -------------------------
__global__ void split_kernel(const float* __restrict__ src,
                             float* __restrict__ hi, float* __restrict__ lo, int n4)
{
    int i = blockIdx.x * blockDim.x + threadIdx.x;
    if (i < n4) {
        float4 v = ((const float4*)src)[i];
        float4 h, l;
        h.x = __uint_as_float(f2tf(v.x)); l.x = __uint_as_float(f2tf(v.x - h.x));
        h.y = __uint_as_float(f2tf(v.y)); l.y = __uint_as_float(f2tf(v.y - h.y));
        h.z = __uint_as_float(f2tf(v.z)); l.z = __uint_as_float(f2tf(v.z - h.z));
        h.w = __uint_as_float(f2tf(v.w)); l.w = __uint_as_float(f2tf(v.w - h.w));
        ((float4*)hi)[i] = h;
        ((float4*)lo)[i] = l;
    }
}

// =========================================================================
// tensor-core GEMM on pre-split operands. C = act(A@W + b).
// 128x128 tile, BK=16, 256 threads (8 warps 2x4), warp tile 64x32, 3xTF32.
// smem layout (floats): AsH[2][128][20] AsL[2][128][20] WsH[2][16][136] WsL[..]
// =========================================================================
#define AS_BUF 2560   // 128*20
#define WS_BUF 2176   // 16*136
#define GEMM_SMEM ((2*AS_BUF*2 + 2*WS_BUF*2) * 4)   // 75776 bytes

template <int ACT, int SPLIT>
__global__ __launch_bounds__(256, 1)
void gemm_tc(const float* __restrict__ Ah, const float* __restrict__ Al,
             const float* __restrict__ Wh, const float* __restrict__ Wl,
             const float* __restrict__ bias,
             float* __restrict__ C, float* __restrict__ Ch, float* __restrict__ Cl,
             int M, int K, int N)
{
    extern __shared__ float dsm[];
    float* AsH = dsm;
    float* AsL = AsH + 2 * AS_BUF;
    float* WsH = AsL + 2 * AS_BUF;
    float* WsL = WsH + 2 * WS_BUF;

    const int tid  = threadIdx.x;
    const int m0   = blockIdx.y * 128;
    const int n0   = blockIdx.x * 128;
    const int warp = tid >> 5, lane = tid & 31;
    const int warpM = warp & 1, warpN = warp >> 1;
    const int mw = warpM * 64;
    const int nw = warpN * 32;
    const int g  = lane >> 2;
    const int tq = lane & 3;

    const int am = tid >> 2;
    const int ak = (tid & 3) * 4;
    const int wk = tid >> 5;
    const int wn = (tid & 31) * 4;
    const size_t aoff = (size_t)(m0 + am) * K + ak;
    const size_t woff = (size_t)wk * N + n0 + wn;

    float acc[4][4][4] = {};

    float4 ah0 = *(const float4*)(Ah + aoff);
    float4 ah1 = *(const float4*)(Ah + aoff + (size_t)64 * K);
    float4 al0 = *(const float4*)(Al + aoff);
    float4 al1 = *(const float4*)(Al + aoff + (size_t)64 * K);
    float4 wh0 = *(const float4*)(Wh + woff);
    float4 wh1 = *(const float4*)(Wh + woff + (size_t)8 * N);
    float4 wl0 = *(const float4*)(Wl + woff);
    float4 wl1 = *(const float4*)(Wl + woff + (size_t)8 * N);
    *(float4*)&AsH[am * 20 + ak]        = ah0;
    *(float4*)&AsH[(am + 64) * 20 + ak] = ah1;
    *(float4*)&AsL[am * 20 + ak]        = al0;
    *(float4*)&AsL[(am + 64) * 20 + ak] = al1;
    *(float4*)&WsH[wk * 136 + wn]       = wh0;
    *(float4*)&WsH[(wk + 8) * 136 + wn] = wh1;
    *(float4*)&WsL[wk * 136 + wn]       = wl0;
    *(float4*)&WsL[(wk + 8) * 136 + wn] = wl1;
    __syncthreads();

    const int KT = K >> 4;
    for (int kt = 0; kt < KT; kt++) {
        const int cur = kt & 1, nxt = cur ^ 1;
        if (kt + 1 < KT) {
            const size_t ao = aoff + (kt + 1) * 16;
            const size_t wo = woff + (size_t)((kt + 1) * 16) * N;
            ah0 = *(const float4*)(Ah + ao);
            ah1 = *(const float4*)(Ah + ao + (size_t)64 * K);
            al0 = *(const float4*)(Al + ao);
            al1 = *(const float4*)(Al + ao + (size_t)64 * K);
            wh0 = *(const float4*)(Wh + wo);
            wh1 = *(const float4*)(Wh + wo + (size_t)8 * N);
            wl0 = *(const float4*)(Wl + wo);
            wl1 = *(const float4*)(Wl + wo + (size_t)8 * N);
        }
        const float* ah = AsH + cur * AS_BUF;
        const float* al = AsL + cur * AS_BUF;
        const float* wh = WsH + cur * WS_BUF;
        const float* wl = WsL + cur * WS_BUF;
        #pragma unroll
        for (int ks = 0; ks < 16; ks += 8) {
            unsigned ahi[4][4], alo[4][4];
            #pragma unroll
            for (int i = 0; i < 4; i++) {
                const int r0 = (mw + i * 16 + g) * 20 + ks + tq;
                const int r1 = r0 + 8 * 20;
                ahi[i][0] = __float_as_uint(ah[r0]);
                ahi[i][1] = __float_as_uint(ah[r1]);
                ahi[i][2] = __float_as_uint(ah[r0 + 4]);
                ahi[i][3] = __float_as_uint(ah[r1 + 4]);
                alo[i][0] = __float_as_uint(al[r0]);
                alo[i][1] = __float_as_uint(al[r1]);
                alo[i][2] = __float_as_uint(al[r0 + 4]);
                alo[i][3] = __float_as_uint(al[r1 + 4]);
            }
            unsigned bhi[4][2], blo[4][2];
            #pragma unroll
            for (int j = 0; j < 4; j++) {
                const int nc = (ks + tq) * 136 + nw + j * 8 + g;
                bhi[j][0] = __float_as_uint(wh[nc]);
                bhi[j][1] = __float_as_uint(wh[nc + 4 * 136]);
                blo[j][0] = __float_as_uint(wl[nc]);
                blo[j][1] = __float_as_uint(wl[nc + 4 * 136]);
            }
            #pragma unroll
            for (int i = 0; i < 4; i++)
                #pragma unroll
                for (int j = 0; j < 4; j++) {
                    mma8(acc[i][j], ahi[i][0], ahi[i][1], ahi[i][2], ahi[i][3], bhi[j][0], bhi[j][1]);
                    mma8(acc[i][j], ahi[i][0], ahi[i][1], ahi[i][2], ahi[i][3], blo[j][0], blo[j][1]);
                    mma8(acc[i][j], alo[i][0], alo[i][1], alo[i][2], alo[i][3], bhi[j][0], bhi[j][1]);
                }
        }
        if (kt + 1 < KT) {
            *(float4*)&AsH[nxt * AS_BUF + am * 20 + ak]        = ah0;
            *(float4*)&AsH[nxt * AS_BUF + (am + 64) * 20 + ak] = ah1;
            *(float4*)&AsL[nxt * AS_BUF + am * 20 + ak]        = al0;
            *(float4*)&AsL[nxt * AS_BUF + (am + 64) * 20 + ak] = al1;
            *(float4*)&WsH[nxt * WS_BUF + wk * 136 + wn]       = wh0;
            *(float4*)&WsH[nxt * WS_BUF + (wk + 8) * 136 + wn] = wh1;
            *(float4*)&WsL[nxt * WS_BUF + wk * 136 + wn]       = wl0;
            *(float4*)&WsL[nxt * WS_BUF + (wk + 8) * 136 + wn] = wl1;
            __syncthreads();
        }
    }

    // epilogue: bias + act (+ split)
    #pragma unroll
    for (int j = 0; j < 4; j++) {
        const int col = n0 + nw + j * 8 + tq * 2;
        const float b0 = bias[col], b1 = bias[col + 1];
        #pragma unroll
        for (int i = 0; i < 4; i++) {
            const int r = m0 + mw + i * 16 + g;
            float v[4];
            v[0] = acc[i][j][0] + b0;
            v[1] = acc[i][j][1] + b1;
            v[2] = acc[i][j][2] + b0;
            v[3] = acc[i][j][3] + b1;
            if (ACT) {
                #pragma unroll
                for (int s = 0; s < 4; s++) v[s] = gelu_exact(v[s]);
            }
            const size_t o0 = (size_t)r * N + col;
            const size_t o1 = (size_t)(r + 8) * N + col;
            if (SPLIT) {
                float h[4], l[4];
                #pragma unroll
                for (int s = 0; s < 4; s++) {
                    h[s] = __uint_as_float(f2tf(v[s]));
                    l[s] = __uint_as_float(f2tf(v[s] - h[s]));
                }
                *(float2*)&Ch[o0] = make_float2(h[0], h[1]);
                *(float2*)&Ch[o1] = make_float2(h[2], h[3]);
                *(float2*)&Cl[o0] = make_float2(l[0], l[1]);
                *(float2*)&Cl[o1] = make_float2(l[2], l[3]);
            } else {
                *(float2*)&C[o0] = make_float2(v[0], v[1]);
                *(float2*)&C[o1] = make_float2(v[2], v[3]);
            }
        }
    }
}

// ------------------------- codebook norms -------------------------
__global__ void code_norm_kernel(const float* __restrict__ cb) {
    int c = blockIdx.x * blockDim.x + threadIdx.x;
    if (c < NCODES) {
        float s = 0.f;
        #pragma unroll 4
        for (int d = 0; d < EMBED; d++) {
            float v = cb[c * EMBED + d];
            s = fmaf(v, v, s);
        }
        g_cnorm[c] = s;
    }
}

__global__ void zero_loss_kernel() { g_loss = 0.0; }

// =========================================================================
// VQ: 128 tokens/block, 1024 codes (8 c-tiles), pre-split operands.
// smem: ZsH[128][132] ZsL[128][132] CsH[2][128][20] CsL[..] cn[1024]
// =========================================================================
#define ZS_N 16896    // 128*132
#define CS_BUF 2560   // 128*20
#define VQ_SMEM ((2 * ZS_N + 2 * 2 * CS_BUF + NCODES) * 4)

__global__ __launch_bounds__(256, 1)
void vq_kernel(const float* __restrict__ zh, const float* __restrict__ zl,
               const float* __restrict__ cbh, const float* __restrict__ cbl,
               const float* __restrict__ cb,
               float* __restrict__ qh, float* __restrict__ ql)
{
    extern __shared__ float dsm[];
    float* ZsH = dsm;
    float* ZsL = ZsH + ZS_N;
    float* CsH = ZsL + ZS_N;
    float* CsL = CsH + 2 * CS_BUF;
    float* cn  = CsL + 2 * CS_BUF;

    __shared__ float red_d[128][4];
    __shared__ int   red_i[128][4];
    __shared__ int   best_idx[128];
    __shared__ float warp_sum[8];

    const int tid = threadIdx.x;
    const int t0  = blockIdx.x * 128;
    const int warp = tid >> 5, lane = tid & 31;
    const int warpM = warp & 1, warpN = warp >> 1;
    const int mw = warpM * 64;
    const int nw = warpN * 32;
    const int g  = lane >> 2;
    const int tq = lane & 3;

    *(float4*)&cn[tid * 4] = *(const float4*)&g_cnorm[tid * 4];

    // z tile (hi/lo) -> smem
    #pragma unroll
    for (int l = 0; l < 16; l++) {
        int idx4 = l * 256 + tid;
        int m = idx4 >> 5;
        int k4 = (idx4 & 31) * 4;
        size_t go = (size_t)(t0 + m) * EMBED + k4;
        *(float4*)&ZsH[m * 132 + k4] = *(const float4*)&zh[go];
        *(float4*)&ZsL[m * 132 + k4] = *(const float4*)&zl[go];
    }

    const int crow = tid >> 2;
    const int ckq  = (tid & 3) * 4;

    float bestD[8];
    int   bestI[8];
    #pragma unroll
    for (int s = 0; s < 8; s++) { bestD[s] = 3.4e38f; bestI[s] = 0; }

    for (int ct = 0; ct < 8; ct++) {
        const int c0 = ct * 128;
        const size_t coff0 = (size_t)(c0 + crow) * EMBED + ckq;
        const size_t coff1 = (size_t)(c0 + crow + 64) * EMBED + ckq;

        float4 ch0 = *(const float4*)(cbh + coff0);
        float4 ch1 = *(const float4*)(cbh + coff1);
        float4 cl0 = *(const float4*)(cbl + coff0);
        float4 cl1 = *(const float4*)(cbl + coff1);
        __syncthreads();
        *(float4*)&CsH[crow * 20 + ckq]        = ch0;
        *(float4*)&CsH[(crow + 64) * 20 + ckq] = ch1;
        *(float4*)&CsL[crow * 20 + ckq]        = cl0;
        *(float4*)&CsL[(crow + 64) * 20 + ckq] = cl1;
        __syncthreads();

        float acc[4][4][4] = {};

        for (int kt = 0; kt < 8; kt++) {
            const int cur = kt & 1, nxt = cur ^ 1;
            if (kt + 1 < 8) {
                ch0 = *(const float4*)(cbh + coff0 + (kt + 1) * 16);
                ch1 = *(const float4*)(cbh + coff1 + (kt + 1) * 16);
                cl0 = *(const float4*)(cbl + coff0 + (kt + 1) * 16);
                cl1 = *(const float4*)(cbl + coff1 + (kt + 1) * 16);
            }
            const float* csh = CsH + cur * CS_BUF;
            const float* csl = CsL + cur * CS_BUF;
            #pragma unroll
            for (int ks = 0; ks < 16; ks += 8) {
                const int kbase = kt * 16 + ks;
                unsigned ahi[4][4], alo[4][4];
                #pragma unroll
                for (int i = 0; i < 4; i++) {
                    const int r0 = (mw + i * 16 + g) * 132 + kbase + tq;
                    const int r1 = r0 + 8 * 132;
                    ahi[i][0] = __float_as_uint(ZsH[r0]);
                    ahi[i][1] = __float_as_uint(ZsH[r1]);
                    ahi[i][2] = __float_as_uint(ZsH[r0 + 4]);
                    ahi[i][3] = __float_as_uint(ZsH[r1 + 4]);
                    alo[i][0] = __float_as_uint(ZsL[r0]);
                    alo[i][1] = __float_as_uint(ZsL[r1]);
                    alo[i][2] = __float_as_uint(ZsL[r0 + 4]);
                    alo[i][3] = __float_as_uint(ZsL[r1 + 4]);
                }
                unsigned bhi[4][2], blo[4][2];
                #pragma unroll
                for (int j = 0; j < 4; j++) {
                    const int nc = (nw + j * 8 + g) * 20 + ks + tq;
                    bhi[j][0] = __float_as_uint(csh[nc]);
                    bhi[j][1] = __float_as_uint(csh[nc + 4]);
                    blo[j][0] = __float_as_uint(csl[nc]);
                    blo[j][1] = __float_as_uint(csl[nc + 4]);
                }
                #pragma unroll
                for (int i = 0; i < 4; i++)
                    #pragma unroll
                    for (int j = 0; j < 4; j++) {
                        mma8(acc[i][j], ahi[i][0], ahi[i][1], ahi[i][2], ahi[i][3], bhi[j][0], bhi[j][1]);
                        mma8(acc[i][j], ahi[i][0], ahi[i][1], ahi[i][2], ahi[i][3], blo[j][0], blo[j][1]);
                        mma8(acc[i][j], alo[i][0], alo[i][1], alo[i][2], alo[i][3], bhi[j][0], bhi[j][1]);
                    }
            }
            if (kt + 1 < 8) {
                *(float4*)&CsH[nxt * CS_BUF + crow * 20 + ckq]        = ch0;
                *(float4*)&CsH[nxt * CS_BUF + (crow + 64) * 20 + ckq] = ch1;
                *(float4*)&CsL[nxt * CS_BUF + crow * 20 + ckq]        = cl0;
                *(float4*)&CsL[nxt * CS_BUF + (crow + 64) * 20 + ckq] = cl1;
                __syncthreads();
            }
        }

        #pragma unroll
        for (int j = 0; j < 4; j++) {
            const int cbase = c0 + nw + j * 8 + tq * 2;
            const float cn0 = cn[cbase], cn1 = cn[cbase + 1];
            #pragma unroll
            for (int i = 0; i < 4; i++) {
                #pragma unroll
                for (int h = 0; h < 2; h++) {
                    const int s = i * 2 + h;
                    float d0 = fmaf(-2.0f, acc[i][j][h * 2 + 0], cn0);
                    float d1 = fmaf(-2.0f, acc[i][j][h * 2 + 1], cn1);
                    if (d0 < bestD[s] || (d0 == bestD[s] && cbase < bestI[s])) { bestD[s] = d0; bestI[s] = cbase; }
                    if (d1 < bestD[s] || (d1 == bestD[s] && cbase + 1 < bestI[s])) { bestD[s] = d1; bestI[s] = cbase + 1; }
                }
            }
        }
    }

    // lane reduction (tq dimension)
    #pragma unroll
    for (int s = 0; s < 8; s++) {
        #pragma unroll
        for (int o = 1; o < 4; o <<= 1) {
            float od = __shfl_xor_sync(0xFFFFFFFFu, bestD[s], o);
            int   oi = __shfl_xor_sync(0xFFFFFFFFu, bestI[s], o);
            if (od < bestD[s] || (od == bestD[s] && oi < bestI[s])) { bestD[s] = od; bestI[s] = oi; }
        }
    }
    if (tq == 0) {
        #pragma unroll
        for (int s = 0; s < 8; s++) {
            const int row = mw + (s >> 1) * 16 + (s & 1) * 8 + g;
            red_d[row][warpN] = bestD[s];
            red_i[row][warpN] = bestI[s];
        }
    }
    __syncthreads();
    if (tid < 128) {
        float bd = red_d[tid][0];
        int   bi = red_i[tid][0];
        #pragma unroll
        for (int x = 1; x < 4; x++) {
            float d = red_d[tid][x];
            int   c = red_i[tid][x];
            if (d < bd || (d == bd && c < bi)) { bd = d; bi = c; }
        }
        best_idx[tid] = bi;
        g_idx[t0 + tid] = bi;
    }
    __syncthreads();

    // gather + straight-through + commit loss; write split q
    float lsum = 0.f;
    #pragma unroll 4
    for (int l = 0; l < 64; l++) {
        int e = l * 256 + tid;
        int trow = e >> 7;
        int d    = e & 127;
        int c    = best_idx[trow];
        float zv   = ZsH[trow * 132 + d] + ZsL[trow * 132 + d];
        float diff = cb[(size_t)c * EMBED + d] - zv;
        float qv   = zv + diff;
        float hh = __uint_as_float(f2tf(qv));
        float ll = __uint_as_float(f2tf(qv - hh));
        size_t go = (size_t)t0 * EMBED + e;
        qh[go] = hh;
        ql[go] = ll;
        lsum = fmaf(diff, diff, lsum);
    }
    #pragma unroll
    for (int o = 16; o > 0; o >>= 1) lsum += __shfl_down_sync(0xFFFFFFFFu, lsum, o);
    if (lane == 0) warp_sum[warp] = lsum;
    __syncthreads();
    if (tid == 0) {
        float s = 0.f;
        #pragma unroll
        for (int w = 0; w < 8; w++) s += warp_sum[w];
        atomicAdd(&g_loss, (double)s);
    }
}

// ------------------------- tail outputs -------------------------
__global__ void finalize_kernel(float* __restrict__ out)
{
    int i = blockIdx.x * 256 + threadIdx.x;
    if (i < NTOKENS_TOTAL) out[REC_ELEMS + i] = (float)g_idx[i];
    if (i == 0) out[REC_ELEMS + NTOKENS_TOTAL] = (float)(g_loss / (double)QELEMS);
}

// ------------------------- launch -------------------------
static void do_split(const float* src, float* hi, float* lo, int n) {
    int n4 = n / 4;
    split_kernel<<<(n4 + 255) / 256, 256>>>(src, hi, lo, n4);
}

extern "C" void kernel_launch(void* const* d_in, const int* in_sizes, int n_in,
                              void* d_out, int out_size)
{
    const float* x   = (const float*)d_in[0];
    const float* eW1 = (const float*)d_in[1];
    const float* eb1 = (const float*)d_in[2];
    const float* eW2 = (const float*)d_in[3];
    const float* eb2 = (const float*)d_in[4];
    const float* eW3 = (const float*)d_in[5];
    const float* eb3 = (const float*)d_in[6];
    const float* dW1 = (const float*)d_in[7];
    const float* db1 = (const float*)d_in[8];
    const float* dW2 = (const float*)d_in[9];
    const float* db2 = (const float*)d_in[10];
    const float* dW3 = (const float*)d_in[11];
    const float* db3 = (const float*)d_in[12];
    const float* cb  = (const float*)d_in[13];
    float* out = (float*)d_out;

    float *xhi, *xlo, *h1hi, *h1lo, *h2hi, *h2lo, *zhi, *zlo, *qhi, *qlo;
    float *h3hi, *h3lo, *h4hi, *h4lo, *whi, *wlo;
    cudaGetSymbolAddress((void**)&xhi,  g_xhi);
    cudaGetSymbolAddress((void**)&xlo,  g_xlo);
    cudaGetSymbolAddress((void**)&h1hi, g_h1hi);
    cudaGetSymbolAddress((void**)&h1lo, g_h1lo);
    cudaGetSymbolAddress((void**)&h2hi, g_h2hi);
    cudaGetSymbolAddress((void**)&h2lo, g_h2lo);
    cudaGetSymbolAddress((void**)&zhi,  g_zhi);
    cudaGetSymbolAddress((void**)&zlo,  g_zlo);
    cudaGetSymbolAddress((void**)&qhi,  g_qhi);
    cudaGetSymbolAddress((void**)&qlo,  g_qlo);
    cudaGetSymbolAddress((void**)&h3hi, g_h3hi);
    cudaGetSymbolAddress((void**)&h3lo, g_h3lo);
    cudaGetSymbolAddress((void**)&h4hi, g_h4hi);
    cudaGetSymbolAddress((void**)&h4lo, g_h4lo);
    cudaGetSymbolAddress((void**)&whi,  g_whi);
    cudaGetSymbolAddress((void**)&wlo,  g_wlo);

    cudaFuncSetAttribute(gemm_tc<1, 1>, cudaFuncAttributeMaxDynamicSharedMemorySize, GEMM_SMEM);
    cudaFuncSetAttribute(gemm_tc<0, 1>, cudaFuncAttributeMaxDynamicSharedMemorySize, GEMM_SMEM);
    cudaFuncSetAttribute(gemm_tc<0, 0>, cudaFuncAttributeMaxDynamicSharedMemorySize, GEMM_SMEM);
    cudaFuncSetAttribute(vq_kernel, cudaFuncAttributeMaxDynamicSharedMemorySize, VQ_SMEM);

    zero_loss_kernel<<<1, 1>>>();
    code_norm_kernel<<<4, 256>>>(cb);

    // prep splits
    do_split(x,   xhi,           xlo,           NB * IN_DIM);
    do_split(eW1, whi + OFF_EW1, wlo + OFF_EW1, IN_DIM * HID);
    do_split(eW2, whi + OFF_EW2, wlo + OFF_EW2, HID * HID);
    do_split(eW3, whi + OFF_EW3, wlo + OFF_EW3, HID * LATENT);
    do_split(dW1, whi + OFF_DW1, wlo + OFF_DW1, LATENT * HID);
    do_split(dW2, whi + OFF_DW2, wlo + OFF_DW2, HID * HID);
    do_split(dW3, whi + OFF_DW3, wlo + OFF_DW3, HID * IN_DIM);
    do_split(cb,  whi + OFF_CB,  wlo + OFF_CB,  NCODES * EMBED);

    // encoder
    gemm_tc<1, 1><<<dim3(HID / 128,    NB / 128), 256, GEMM_SMEM>>>(
        xhi, xlo, whi + OFF_EW1, wlo + OFF_EW1, eb1, nullptr, h1hi, h1lo, NB, IN_DIM, HID);
    gemm_tc<1, 1><<<dim3(HID / 128,    NB / 128), 256, GEMM_SMEM>>>(
        h1hi, h1lo, whi + OFF_EW2, wlo + OFF_EW2, eb2, nullptr, h2hi, h2lo, NB, HID, HID);
    gemm_tc<0, 1><<<dim3(LATENT / 128, NB / 128), 256, GEMM_SMEM>>>(
        h2hi, h2lo, whi + OFF_EW3, wlo + OFF_EW3, eb3, nullptr, zhi, zlo, NB, HID, LATENT);

    // VQ
    vq_kernel<<<NTOKENS_TOTAL / 128, 256, VQ_SMEM>>>(
        zhi, zlo, whi + OFF_CB, wlo + OFF_CB, cb, qhi, qlo);

    // decoder
    gemm_tc<1, 1><<<dim3(HID / 128,    NB / 128), 256, GEMM_SMEM>>>(
        qhi, qlo, whi + OFF_DW1, wlo + OFF_DW1, db1, nullptr, h3hi, h3lo, NB, LATENT, HID);
    gemm_tc<1, 1><<<dim3(HID / 128,    NB / 128), 256, GEMM_SMEM>>>(
        h3hi, h3lo, whi + OFF_DW2, wlo + OFF_DW2, db2, nullptr, h4hi, h4lo, NB, HID, HID);
    gemm_tc<0, 0><<<dim3(IN_DIM / 128, NB / 128), 256, GEMM_SMEM>>>(
        h4hi, h4lo, whi + OFF_DW3, wlo + OFF_DW3, db3, out, nullptr, nullptr, NB, HID, IN_DIM);

    if (out_size >= REC_ELEMS + NTOKENS_TOTAL + 1)
        finalize_kernel<<<(NTOKENS_TOTAL + 255) / 256, 256>>>(out);
}

// round 5
// speedup vs baseline: 1.8752x; 1.8752x over previous
#include <cuda_runtime.h>
#include <cuda_bf16.h>
#include <math.h>

#define NB 4096
#define IN_DIM 1024
#define HID 512
#define EMBED 128
#define NTOK 16
#define NCODES 1024
#define LATENT 2048
#define NTOKENS_TOTAL (NB * NTOK)          // 65536
#define QELEMS (NTOKENS_TOTAL * EMBED)     // 8388608
#define REC_ELEMS (NB * IN_DIM)            // 4194304

// weight pool offsets (elements) — transposed [N][K] layouts
#define OFF_EW1 0
#define OFF_EW2 524288
#define OFF_EW3 786432
#define OFF_DW1 1835008
#define OFF_DW2 2883584
#define OFF_DW3 3145728
#define OFF_CB  3670016
#define WPOOL_N 3801088

// ------------------------- scratch -------------------------
__device__ __nv_bfloat16 g_xh[NB * IN_DIM];
__device__ __nv_bfloat16 g_xl[NB * IN_DIM];
__device__ __nv_bfloat16 g_h1h[NB * HID];
__device__ __nv_bfloat16 g_h1l[NB * HID];
__device__ __nv_bfloat16 g_h2h[NB * HID];
__device__ __nv_bfloat16 g_h2l[NB * HID];
__device__ __nv_bfloat16 g_zh[NB * LATENT];
__device__ __nv_bfloat16 g_zl[NB * LATENT];
__device__ __nv_bfloat16 g_qh[NB * LATENT];
__device__ __nv_bfloat16 g_ql[NB * LATENT];
__device__ __nv_bfloat16 g_h3h[NB * HID];
__device__ __nv_bfloat16 g_h3l[NB * HID];
__device__ __nv_bfloat16 g_h4h[NB * HID];
__device__ __nv_bfloat16 g_h4l[NB * HID];
__device__ __nv_bfloat16 g_wh[WPOOL_N];
__device__ __nv_bfloat16 g_wl[WPOOL_N];
__device__ float  g_cnorm[NCODES];
__device__ int    g_idx[NTOKENS_TOTAL];
__device__ double g_loss;

__device__ __forceinline__ float gelu_exact(float x) {
    return 0.5f * x * (1.0f + erff(x * 0.70710678118654752440f));
}

__device__ __forceinline__ void mma16(float* d,
                                      unsigned a0, unsigned a1, unsigned a2, unsigned a3,
                                      unsigned b0, unsigned b1) {
    asm volatile(
        "mma.sync.aligned.m16n8k16.row.col.f32.bf16.bf16.f32 "
        "{%0,%1,%2,%3},{%4,%5,%6,%7},{%8,%9},{%0,%1,%2,%3};"
        : "+f"(d[0]), "+f"(d[1]), "+f"(d[2]), "+f"(d[3])
        : "r"(a0), "r"(a1), "r"(a2), "r"(a3), "r"(b0), "r"(b1));
}

__device__ __forceinline__ void cpa16(__nv_bfloat16* dst, const __nv_bfloat16* src) {
    unsigned a = (unsigned)__cvta_generic_to_shared(dst);
    asm volatile("cp.async.cg.shared.global [%0], [%1], 16;" :: "r"(a), "l"(src));
}
#define CPA_COMMIT() asm volatile("cp.async.commit_group;")
#define CPA_WAIT0()  asm volatile("cp.async.wait_group 0;")

// ------------------------- prep kernels -------------------------
// elementwise split (same layout)
__global__ void pack_plane(const float* __restrict__ src,
                           __nv_bfloat16* __restrict__ hi, __nv_bfloat16* __restrict__ lo,
                           int n4)
{
    int i = blockIdx.x * blockDim.x + threadIdx.x;
    if (i < n4) {
        float4 v = ((const float4*)src)[i];
        __nv_bfloat16 h0 = __float2bfloat16(v.x);
        __nv_bfloat16 h1 = __float2bfloat16(v.y);
        __nv_bfloat16 h2 = __float2bfloat16(v.z);
        __nv_bfloat16 h3 = __float2bfloat16(v.w);
        __nv_bfloat162 hh0; hh0.x = h0; hh0.y = h1;
        __nv_bfloat162 hh1; hh1.x = h2; hh1.y = h3;
        __nv_bfloat162 ll0;
        ll0.x = __float2bfloat16(v.x - __bfloat162float(h0));
        ll0.y = __float2bfloat16(v.y - __bfloat162float(h1));
        __nv_bfloat162 ll1;
        ll1.x = __float2bfloat16(v.z - __bfloat162float(h2));
        ll1.y = __float2bfloat16(v.w - __bfloat162float(h3));
        ((__nv_bfloat162*)hi)[i * 2]     = hh0;
        ((__nv_bfloat162*)hi)[i * 2 + 1] = hh1;
        ((__nv_bfloat162*)lo)[i * 2]     = ll0;
        ((__nv_bfloat162*)lo)[i * 2 + 1] = ll1;
    }
}

// transpose + split: W [K][N] fp32 -> out [N][K] bf16 planes
__global__ void pack_wT(const float* __restrict__ W,
                        __nv_bfloat16* __restrict__ hi, __nv_bfloat16* __restrict__ lo,
                        int K, int N)
{
    __shared__ float t[32][33];
    const int n0 = blockIdx.x * 32, k0 = blockIdx.y * 32;
    const int tx = threadIdx.x, ty = threadIdx.y;   // (32, 8)
    #pragma unroll
    for (int r = 0; r < 32; r += 8)
        t[ty + r][tx] = W[(size_t)(k0 + ty + r) * N + n0 + tx];
    __syncthreads();
    #pragma unroll
    for (int r = 0; r < 32; r += 8) {
        float v = t[tx][ty + r];
        size_t o = (size_t)(n0 + ty + r) * K + k0 + tx;
        __nv_bfloat16 h = __float2bfloat16(v);
        hi[o] = h;
        lo[o] = __float2bfloat16(v - __bfloat162float(h));
    }
}

__global__ void code_norm_kernel(const float* __restrict__ cb) {
    int c = blockIdx.x * blockDim.x + threadIdx.x;
    if (c < NCODES) {
        float s = 0.f;
        #pragma unroll 4
        for (int d = 0; d < EMBED; d++) {
            float v = cb[c * EMBED + d];
            s = fmaf(v, v, s);
        }
        g_cnorm[c] = s;
    }
}

__global__ void zero_loss_kernel() { g_loss = 0.0; }

// =========================================================================
// bf16 3-term GEMM: C = act(A@W + b)
// A planes [M][K] bf16 (row-major), W planes [N][K] bf16 (k-major).
// 128x128 tile, BK=32, 256 threads (8 warps 2x4), warp 64x32, m16n8k16.
// =========================================================================
#define GAS 5120   // 128*40 bf16 per plane buffer
#define GEMM_SMEM (8 * GAS * 2)   // 81920 bytes

template <int ACT, int SPLIT>
__global__ __launch_bounds__(256, 1)
void gemm_bf(const __nv_bfloat16* __restrict__ Ah, const __nv_bfloat16* __restrict__ Al,
             const __nv_bfloat16* __restrict__ Wh, const __nv_bfloat16* __restrict__ Wl,
             const float* __restrict__ bias,
             float* __restrict__ C,
             __nv_bfloat16* __restrict__ Ch, __nv_bfloat16* __restrict__ Cl,
             int M, int K, int N)
{
    extern __shared__ __align__(16) char smraw[];
    __nv_bfloat16* sm  = (__nv_bfloat16*)smraw;
    __nv_bfloat16* AsH = sm;               // [2][GAS]
    __nv_bfloat16* AsL = sm + 2 * GAS;
    __nv_bfloat16* WsH = sm + 4 * GAS;
    __nv_bfloat16* WsL = sm + 6 * GAS;

    const int tid  = threadIdx.x;
    const int m0   = blockIdx.y * 128;
    const int n0   = blockIdx.x * 128;
    const int warp = tid >> 5, lane = tid & 31;
    const int mw = (warp & 1) * 64;
    const int nw = (warp >> 1) * 32;
    const int g  = lane >> 2;
    const int tq = lane & 3;

    // global staging mapping: thread t -> rows t>>2 and (t>>2)+64, f4 chunk (t&3)*8
    const int srow = tid >> 2;
    const int sfq  = (tid & 3) * 8;
    const size_t aoff = (size_t)(m0 + srow) * K + sfq;
    const size_t woff = (size_t)(n0 + srow) * K + sfq;
    const int s_lo = srow * 40 + sfq;
    const int s_hi = (srow + 64) * 40 + sfq;

    float acc[4][4][4] = {};

    float4 ah0 = *(const float4*)(Ah + aoff);
    float4 ah1 = *(const float4*)(Ah + aoff + (size_t)64 * K);
    float4 al0 = *(const float4*)(Al + aoff);
    float4 al1 = *(const float4*)(Al + aoff + (size_t)64 * K);
    float4 wh0 = *(const float4*)(Wh + woff);
    float4 wh1 = *(const float4*)(Wh + woff + (size_t)64 * K);
    float4 wl0 = *(const float4*)(Wl + woff);
    float4 wl1 = *(const float4*)(Wl + woff + (size_t)64 * K);
    *(float4*)&AsH[s_lo] = ah0;  *(float4*)&AsH[s_hi] = ah1;
    *(float4*)&AsL[s_lo] = al0;  *(float4*)&AsL[s_hi] = al1;
    *(float4*)&WsH[s_lo] = wh0;  *(float4*)&WsH[s_hi] = wh1;
    *(float4*)&WsL[s_lo] = wl0;  *(float4*)&WsL[s_hi] = wl1;
    __syncthreads();

    const int KT = K >> 5;
    for (int kt = 0; kt < KT; kt++) {
        const int cur = kt & 1, nxt = cur ^ 1;
        if (kt + 1 < KT) {
            const size_t ao = aoff + (kt + 1) * 32;
            const size_t wo = woff + (kt + 1) * 32;
            ah0 = *(const float4*)(Ah + ao);
            ah1 = *(const float4*)(Ah + ao + (size_t)64 * K);
            al0 = *(const float4*)(Al + ao);
            al1 = *(const float4*)(Al + ao + (size_t)64 * K);
            wh0 = *(const float4*)(Wh + wo);
            wh1 = *(const float4*)(Wh + wo + (size_t)64 * K);
            wl0 = *(const float4*)(Wl + wo);
            wl1 = *(const float4*)(Wl + wo + (size_t)64 * K);
        }
        const __nv_bfloat16* ah = AsH + cur * GAS;
        const __nv_bfloat16* al = AsL + cur * GAS;
        const __nv_bfloat16* wh = WsH + cur * GAS;
        const __nv_bfloat16* wl = WsL + cur * GAS;
        #pragma unroll
        for (int ks = 0; ks < 32; ks += 16) {
            unsigned ahr[4][4], alr[4][4];
            #pragma unroll
            for (int i = 0; i < 4; i++) {
                const int b = (mw + i * 16 + g) * 40 + ks + 2 * tq;
                ahr[i][0] = *(const unsigned*)(ah + b);
                ahr[i][1] = *(const unsigned*)(ah + b + 8 * 40);
                ahr[i][2] = *(const unsigned*)(ah + b + 8);
                ahr[i][3] = *(const unsigned*)(ah + b + 8 * 40 + 8);
                alr[i][0] = *(const unsigned*)(al + b);
                alr[i][1] = *(const unsigned*)(al + b + 8 * 40);
                alr[i][2] = *(const unsigned*)(al + b + 8);
                alr[i][3] = *(const unsigned*)(al + b + 8 * 40 + 8);
            }
            unsigned bhr[4][2], blr[4][2];
            #pragma unroll
            for (int j = 0; j < 4; j++) {
                const int b = (nw + j * 8 + g) * 40 + ks + 2 * tq;
                bhr[j][0] = *(const unsigned*)(wh + b);
                bhr[j][1] = *(const unsigned*)(wh + b + 8);
                blr[j][0] = *(const unsigned*)(wl + b);
                blr[j][1] = *(const unsigned*)(wl + b + 8);
            }
            #pragma unroll
            for (int i = 0; i < 4; i++)
                #pragma unroll
                for (int j = 0; j < 4; j++) {
                    mma16(acc[i][j], ahr[i][0], ahr[i][1], ahr[i][2], ahr[i][3], bhr[j][0], bhr[j][1]);
                    mma16(acc[i][j], ahr[i][0], ahr[i][1], ahr[i][2], ahr[i][3], blr[j][0], blr[j][1]);
                    mma16(acc[i][j], alr[i][0], alr[i][1], alr[i][2], alr[i][3], bhr[j][0], bhr[j][1]);
                }
        }
        if (kt + 1 < KT) {
            *(float4*)&AsH[nxt * GAS + s_lo] = ah0;  *(float4*)&AsH[nxt * GAS + s_hi] = ah1;
            *(float4*)&AsL[nxt * GAS + s_lo] = al0;  *(float4*)&AsL[nxt * GAS + s_hi] = al1;
            *(float4*)&WsH[nxt * GAS + s_lo] = wh0;  *(float4*)&WsH[nxt * GAS + s_hi] = wh1;
            *(float4*)&WsL[nxt * GAS + s_lo] = wl0;  *(float4*)&WsL[nxt * GAS + s_hi] = wl1;
            __syncthreads();
        }
    }

    // epilogue
    #pragma unroll
    for (int j = 0; j < 4; j++) {
        const int col = n0 + nw + j * 8 + tq * 2;
        const float b0 = bias[col], b1 = bias[col + 1];
        #pragma unroll
        for (int i = 0; i < 4; i++) {
            const int r = m0 + mw + i * 16 + g;
            float v0 = acc[i][j][0] + b0;
            float v1 = acc[i][j][1] + b1;
            float v2 = acc[i][j][2] + b0;
            float v3 = acc[i][j][3] + b1;
            if (ACT) { v0 = gelu_exact(v0); v1 = gelu_exact(v1); v2 = gelu_exact(v2); v3 = gelu_exact(v3); }
            const size_t o0 = (size_t)r * N + col;
            const size_t o1 = (size_t)(r + 8) * N + col;
            if (SPLIT) {
                __nv_bfloat16 h0 = __float2bfloat16(v0), h1 = __float2bfloat16(v1);
                __nv_bfloat16 h2 = __float2bfloat16(v2), h3 = __float2bfloat16(v3);
                __nv_bfloat162 hh0; hh0.x = h0; hh0.y = h1;
                __nv_bfloat162 hh1; hh1.x = h2; hh1.y = h3;
                __nv_bfloat162 ll0;
                ll0.x = __float2bfloat16(v0 - __bfloat162float(h0));
                ll0.y = __float2bfloat16(v1 - __bfloat162float(h1));
                __nv_bfloat162 ll1;
                ll1.x = __float2bfloat16(v2 - __bfloat162float(h2));
                ll1.y = __float2bfloat16(v3 - __bfloat162float(h3));
                *(__nv_bfloat162*)&Ch[o0] = hh0;
                *(__nv_bfloat162*)&Ch[o1] = hh1;
                *(__nv_bfloat162*)&Cl[o0] = ll0;
                *(__nv_bfloat162*)&Cl[o1] = ll1;
            } else {
                *(float2*)&C[o0] = make_float2(v0, v1);
                *(float2*)&C[o1] = make_float2(v2, v3);
            }
        }
    }
}

// =========================================================================
// VQ: 128 tokens/block, 1024 codes, bf16 3-term distances via m16n8k16.
// smem (bf16 units): ZsH[17408] ZsL[17408] Cs[2 buf][H+L 2x17408] cn fp32
// =========================================================================
#define ZPS 17408            // 128*136
#define VQ_SMEM (((size_t)6 * ZPS) * 2 + NCODES * 4)   // 208896 + 4096 bytes

__global__ __launch_bounds__(256, 1)
void vq_kernel(const __nv_bfloat16* __restrict__ zh, const __nv_bfloat16* __restrict__ zl,
               const __nv_bfloat16* __restrict__ cbh, const __nv_bfloat16* __restrict__ cbl,
               const float* __restrict__ cb,
               __nv_bfloat16* __restrict__ qh, __nv_bfloat16* __restrict__ ql)
{
    extern __shared__ __align__(16) char smraw[];
    __nv_bfloat16* sm  = (__nv_bfloat16*)smraw;
    __nv_bfloat16* ZsH = sm;
    __nv_bfloat16* ZsL = sm + ZPS;
    __nv_bfloat16* Cb  = sm + 2 * ZPS;        // [buf][2 planes][17408]
    float* cn = (float*)(sm + 6 * ZPS);

    __shared__ float red_d[128][4];
    __shared__ int   red_i[128][4];
    __shared__ int   best_idx[128];
    __shared__ float warp_sum[8];

    const int tid = threadIdx.x;
    const int t0  = blockIdx.x * 128;
    const int warp = tid >> 5, lane = tid & 31;
    const int mw = (warp & 1) * 64;
    const int nw = (warp >> 1) * 32;
    const int g  = lane >> 2;
    const int tq = lane & 3;

    *(float4*)&cn[tid * 4] = *(const float4*)&g_cnorm[tid * 4];

    // async load z planes + c-tile 0
    #pragma unroll
    for (int l = 0; l < 8; l++) {
        int idx = l * 256 + tid;
        int row = idx >> 4, c16 = (idx & 15) * 8;
        cpa16(ZsH + row * 136 + c16, zh + (size_t)(t0 + row) * EMBED + c16);
        cpa16(ZsL + row * 136 + c16, zl + (size_t)(t0 + row) * EMBED + c16);
        cpa16(Cb + row * 136 + c16,        cbh + (size_t)row * EMBED + c16);
        cpa16(Cb + ZPS + row * 136 + c16,  cbl + (size_t)row * EMBED + c16);
    }
    CPA_COMMIT();
    CPA_WAIT0();
    __syncthreads();

    float bestD[8];
    int   bestI[8];
    #pragma unroll
    for (int s = 0; s < 8; s++) { bestD[s] = 3.4e38f; bestI[s] = 0; }

    for (int ct = 0; ct < 8; ct++) {
        const int cur = ct & 1, nxt = cur ^ 1;
        const __nv_bfloat16* csh = Cb + cur * 2 * ZPS;
        const __nv_bfloat16* csl = csh + ZPS;

        if (ct < 7) {
            const int c0n = (ct + 1) * 128;
            __nv_bfloat16* dH = Cb + nxt * 2 * ZPS;
            __nv_bfloat16* dL = dH + ZPS;
            #pragma unroll
            for (int l = 0; l < 8; l++) {
                int idx = l * 256 + tid;
                int row = idx >> 4, c16 = (idx & 15) * 8;
                cpa16(dH + row * 136 + c16, cbh + (size_t)(c0n + row) * EMBED + c16);
                cpa16(dL + row * 136 + c16, cbl + (size_t)(c0n + row) * EMBED + c16);
            }
            CPA_COMMIT();
        }

        float acc[4][4][4] = {};
        #pragma unroll
        for (int kt = 0; kt < 8; kt++) {
            const int kb = kt * 16;
            unsigned ahr[4][4], alr[4][4];
            #pragma unroll
            for (int i = 0; i < 4; i++) {
                const int b = (mw + i * 16 + g) * 136 + kb + 2 * tq;
                ahr[i][0] = *(const unsigned*)(ZsH + b);
                ahr[i][1] = *(const unsigned*)(ZsH + b + 8 * 136);
                ahr[i][2] = *(const unsigned*)(ZsH + b + 8);
                ahr[i][3] = *(const unsigned*)(ZsH + b + 8 * 136 + 8);
                alr[i][0] = *(const unsigned*)(ZsL + b);
                alr[i][1] = *(const unsigned*)(ZsL + b + 8 * 136);
                alr[i][2] = *(const unsigned*)(ZsL + b + 8);
                alr[i][3] = *(const unsigned*)(ZsL + b + 8 * 136 + 8);
            }
            unsigned bhr[4][2], blr[4][2];
            #pragma unroll
            for (int j = 0; j < 4; j++) {
                const int b = (nw + j * 8 + g) * 136 + kb + 2 * tq;
                bhr[j][0] = *(const unsigned*)(csh + b);
                bhr[j][1] = *(const unsigned*)(csh + b + 8);
                blr[j][0] = *(const unsigned*)(csl + b);
                blr[j][1] = *(const unsigned*)(csl + b + 8);
            }
            #pragma unroll
            for (int i = 0; i < 4; i++)
                #pragma unroll
                for (int j = 0; j < 4; j++) {
                    mma16(acc[i][j], ahr[i][0], ahr[i][1], ahr[i][2], ahr[i][3], bhr[j][0], bhr[j][1]);
                    mma16(acc[i][j], ahr[i][0], ahr[i][1], ahr[i][2], ahr[i][3], blr[j][0], blr[j][1]);
                    mma16(acc[i][j], alr[i][0], alr[i][1], alr[i][2], alr[i][3], bhr[j][0], bhr[j][1]);
                }
        }

        // argmin update
        const int c0 = ct * 128;
        #pragma unroll
        for (int j = 0; j < 4; j++) {
            const int cbase = c0 + nw + j * 8 + tq * 2;
            const float cn0 = cn[cbase - c0 + c0], cn1 = cn[cbase + 1];
            #pragma unroll
            for (int i = 0; i < 4; i++) {
                #pragma unroll
                for (int h = 0; h < 2; h++) {
                    const int s = i * 2 + h;
                    float d0 = fmaf(-2.0f, acc[i][j][h * 2 + 0], cn0);
                    float d1 = fmaf(-2.0f, acc[i][j][h * 2 + 1], cn1);
                    if (d0 < bestD[s] || (d0 == bestD[s] && cbase < bestI[s])) { bestD[s] = d0; bestI[s] = cbase; }
                    if (d1 < bestD[s] || (d1 == bestD[s] && cbase + 1 < bestI[s])) { bestD[s] = d1; bestI[s] = cbase + 1; }
                }
            }
        }

        if (ct < 7) {
            CPA_WAIT0();
            __syncthreads();
        }
    }

    // lane reduction across tq
    #pragma unroll
    for (int s = 0; s < 8; s++) {
        #pragma unroll
        for (int o = 1; o < 4; o <<= 1) {
            float od = __shfl_xor_sync(0xFFFFFFFFu, bestD[s], o);
            int   oi = __shfl_xor_sync(0xFFFFFFFFu, bestI[s], o);
            if (od < bestD[s] || (od == bestD[s] && oi < bestI[s])) { bestD[s] = od; bestI[s] = oi; }
        }
    }
    if (tq == 0) {
        #pragma unroll
        for (int s = 0; s < 8; s++) {
            const int row = mw + (s >> 1) * 16 + (s & 1) * 8 + g;
            red_d[row][warp >> 1] = bestD[s];
            red_i[row][warp >> 1] = bestI[s];
        }
    }
    __syncthreads();
    if (tid < 128) {
        float bd = red_d[tid][0];
        int   bi = red_i[tid][0];
        #pragma unroll
        for (int x = 1; x < 4; x++) {
            float d = red_d[tid][x];
            int   c = red_i[tid][x];
            if (d < bd || (d == bd && c < bi)) { bd = d; bi = c; }
        }
        best_idx[tid] = bi;
        g_idx[t0 + tid] = bi;
    }
    __syncthreads();

    // gather + straight-through + commit loss
    float lsum = 0.f;
    #pragma unroll 4
    for (int l = 0; l < 64; l++) {
        int e = l * 256 + tid;
        int trow = e >> 7;
        int d    = e & 127;
        int c    = best_idx[trow];
        float zv = __bfloat162float(ZsH[trow * 136 + d]) + __bfloat162float(ZsL[trow * 136 + d]);
        float diff = cb[(size_t)c * EMBED + d] - zv;
        float qv = zv + diff;
        __nv_bfloat16 hh = __float2bfloat16(qv);
        size_t go = (size_t)t0 * EMBED + e;
        qh[go] = hh;
        ql[go] = __float2bfloat16(qv - __bfloat162float(hh));
        lsum = fmaf(diff, diff, lsum);
    }
    #pragma unroll
    for (int o = 16; o > 0; o >>= 1) lsum += __shfl_down_sync(0xFFFFFFFFu, lsum, o);
    if (lane == 0) warp_sum[warp] = lsum;
    __syncthreads();
    if (tid == 0) {
        float s = 0.f;
        #pragma unroll
        for (int w = 0; w < 8; w++) s += warp_sum[w];
        atomicAdd(&g_loss, (double)s);
    }
}

// ------------------------- tail outputs -------------------------
__global__ void finalize_kernel(float* __restrict__ out)
{
    int i = blockIdx.x * 256 + threadIdx.x;
    if (i < NTOKENS_TOTAL) out[REC_ELEMS + i] = (float)g_idx[i];
    if (i == 0) out[REC_ELEMS + NTOKENS_TOTAL] = (float)(g_loss / (double)QELEMS);
}

// ------------------------- launch -------------------------
extern "C" void kernel_launch(void* const* d_in, const int* in_sizes, int n_in,
                              void* d_out, int out_size)
{
    const float* x   = (const float*)d_in[0];
    const float* eW1 = (const float*)d_in[1];
    const float* eb1 = (const float*)d_in[2];
    const float* eW2 = (const float*)d_in[3];
    const float* eb2 = (const float*)d_in[4];
    const float* eW3 = (const float*)d_in[5];
    const float* eb3 = (const float*)d_in[6];
    const float* dW1 = (const float*)d_in[7];
    const float* db1 = (const float*)d_in[8];
    const float* dW2 = (const float*)d_in[9];
    const float* db2 = (const float*)d_in[10];
    const float* dW3 = (const float*)d_in[11];
    const float* db3 = (const float*)d_in[12];
    const float* cb  = (const float*)d_in[13];
    float* out = (float*)d_out;

    __nv_bfloat16 *xh, *xl, *h1h, *h1l, *h2h, *h2l, *zh, *zl, *qh, *ql;
    __nv_bfloat16 *h3h, *h3l, *h4h, *h4l, *wh, *wl;
    cudaGetSymbolAddress((void**)&xh,  g_xh);
    cudaGetSymbolAddress((void**)&xl,  g_xl);
    cudaGetSymbolAddress((void**)&h1h, g_h1h);
    cudaGetSymbolAddress((void**)&h1l, g_h1l);
    cudaGetSymbolAddress((void**)&h2h, g_h2h);
    cudaGetSymbolAddress((void**)&h2l, g_h2l);
    cudaGetSymbolAddress((void**)&zh,  g_zh);
    cudaGetSymbolAddress((void**)&zl,  g_zl);
    cudaGetSymbolAddress((void**)&qh,  g_qh);
    cudaGetSymbolAddress((void**)&ql,  g_ql);
    cudaGetSymbolAddress((void**)&h3h, g_h3h);
    cudaGetSymbolAddress((void**)&h3l, g_h3l);
    cudaGetSymbolAddress((void**)&h4h, g_h4h);
    cudaGetSymbolAddress((void**)&h4l, g_h4l);
    cudaGetSymbolAddress((void**)&wh,  g_wh);
    cudaGetSymbolAddress((void**)&wl,  g_wl);

    cudaFuncSetAttribute(gemm_bf<1, 1>, cudaFuncAttributeMaxDynamicSharedMemorySize, GEMM_SMEM);
    cudaFuncSetAttribute(gemm_bf<0, 1>, cudaFuncAttributeMaxDynamicSharedMemorySize, GEMM_SMEM);
    cudaFuncSetAttribute(gemm_bf<0, 0>, cudaFuncAttributeMaxDynamicSharedMemorySize, GEMM_SMEM);
    cudaFuncSetAttribute(vq_kernel, cudaFuncAttributeMaxDynamicSharedMemorySize, (int)VQ_SMEM);

    zero_loss_kernel<<<1, 1>>>();
    code_norm_kernel<<<4, 256>>>(cb);

    // prep: x + codebook elementwise; weights transposed to [N][K]
    pack_plane<<<(NB * IN_DIM / 4 + 255) / 256, 256>>>(x,  xh, xl, NB * IN_DIM / 4);
    pack_plane<<<(NCODES * EMBED / 4 + 255) / 256, 256>>>(cb, wh + OFF_CB, wl + OFF_CB, NCODES * EMBED / 4);
    dim3 tb(32, 8);
    pack_wT<<<dim3(HID / 32,    IN_DIM / 32), tb>>>(eW1, wh + OFF_EW1, wl + OFF_EW1, IN_DIM, HID);
    pack_wT<<<dim3(HID / 32,    HID / 32),    tb>>>(eW2, wh + OFF_EW2, wl + OFF_EW2, HID,    HID);
    pack_wT<<<dim3(LATENT / 32, HID / 32),    tb>>>(eW3, wh + OFF_EW3, wl + OFF_EW3, HID,    LATENT);
    pack_wT<<<dim3(HID / 32,    LATENT / 32), tb>>>(dW1, wh + OFF_DW1, wl + OFF_DW1, LATENT, HID);
    pack_wT<<<dim3(HID / 32,    HID / 32),    tb>>>(dW2, wh + OFF_DW2, wl + OFF_DW2, HID,    HID);
    pack_wT<<<dim3(IN_DIM / 32, HID / 32),    tb>>>(dW3, wh + OFF_DW3, wl + OFF_DW3, HID,    IN_DIM);

    // encoder
    gemm_bf<1, 1><<<dim3(HID / 128,    NB / 128), 256, GEMM_SMEM>>>(
        xh, xl, wh + OFF_EW1, wl + OFF_EW1, eb1, nullptr, h1h, h1l, NB, IN_DIM, HID);
    gemm_bf<1, 1><<<dim3(HID / 128,    NB / 128), 256, GEMM_SMEM>>>(
        h1h, h1l, wh + OFF_EW2, wl + OFF_EW2, eb2, nullptr, h2h, h2l, NB, HID, HID);
    gemm_bf<0, 1><<<dim3(LATENT / 128, NB / 128), 256, GEMM_SMEM>>>(
        h2h, h2l, wh + OFF_EW3, wl + OFF_EW3, eb3, nullptr, zh, zl, NB, HID, LATENT);

    // VQ
    vq_kernel<<<NTOKENS_TOTAL / 128, 256, VQ_SMEM>>>(
        zh, zl, wh + OFF_CB, wl + OFF_CB, cb, qh, ql);

    // decoder
    gemm_bf<1, 1><<<dim3(HID / 128,    NB / 128), 256, GEMM_SMEM>>>(
        qh, ql, wh + OFF_DW1, wl + OFF_DW1, db1, nullptr, h3h, h3l, NB, LATENT, HID);
    gemm_bf<1, 1><<<dim3(HID / 128,    NB / 128), 256, GEMM_SMEM>>>(
        h3h, h3l, wh + OFF_DW2, wl + OFF_DW2, db2, nullptr, h4h, h4l, NB, HID, HID);
    gemm_bf<0, 0><<<dim3(IN_DIM / 128, NB / 128), 256, GEMM_SMEM>>>(
        h4h, h4l, wh + OFF_DW3, wl + OFF_DW3, db3, out, nullptr, nullptr, NB, HID, IN_DIM);

    if (out_size >= REC_ELEMS + NTOKENS_TOTAL + 1)
        finalize_kernel<<<(NTOKENS_TOTAL + 255) / 256, 256>>>(out);
}

// round 6
// speedup vs baseline: 2.0254x; 1.0801x over previous
#include <cuda_runtime.h>
#include <cuda_bf16.h>
#include <math.h>

#define NB 4096
#define IN_DIM 1024
#define HID 512
#define EMBED 128
#define NTOK 16
#define NCODES 1024
#define LATENT 2048
#define NTOKENS_TOTAL (NB * NTOK)          // 65536
#define QELEMS (NTOKENS_TOTAL * EMBED)     // 8388608
#define REC_ELEMS (NB * IN_DIM)            // 4194304

// weight pool offsets (elements) — transposed [N][K] layouts
#define OFF_EW1 0
#define OFF_EW2 524288
#define OFF_EW3 786432
#define OFF_DW1 1835008
#define OFF_DW2 2883584
#define OFF_DW3 3145728
#define OFF_CB  3670016
#define WPOOL_N 3801088

// ------------------------- scratch -------------------------
__device__ __nv_bfloat16 g_xh[NB * IN_DIM];
__device__ __nv_bfloat16 g_xl[NB * IN_DIM];
__device__ __nv_bfloat16 g_h1h[NB * HID];
__device__ __nv_bfloat16 g_h1l[NB * HID];
__device__ __nv_bfloat16 g_h2h[NB * HID];
__device__ __nv_bfloat16 g_h2l[NB * HID];
__device__ __nv_bfloat16 g_zh[NB * LATENT];
__device__ __nv_bfloat16 g_zl[NB * LATENT];
__device__ __nv_bfloat16 g_qh[NB * LATENT];
__device__ __nv_bfloat16 g_ql[NB * LATENT];
__device__ __nv_bfloat16 g_h3h[NB * HID];
__device__ __nv_bfloat16 g_h3l[NB * HID];
__device__ __nv_bfloat16 g_h4h[NB * HID];
__device__ __nv_bfloat16 g_h4l[NB * HID];
__device__ __nv_bfloat16 g_wh[WPOOL_N];
__device__ __nv_bfloat16 g_wl[WPOOL_N];
__device__ float  g_cnorm[NCODES];
__device__ int    g_idx[NTOKENS_TOTAL];
__device__ double g_loss;

__device__ __forceinline__ float gelu_exact(float x) {
    return 0.5f * x * (1.0f + erff(x * 0.70710678118654752440f));
}

__device__ __forceinline__ void mma16(float* d,
                                      unsigned a0, unsigned a1, unsigned a2, unsigned a3,
                                      unsigned b0, unsigned b1) {
    asm volatile(
        "mma.sync.aligned.m16n8k16.row.col.f32.bf16.bf16.f32 "
        "{%0,%1,%2,%3},{%4,%5,%6,%7},{%8,%9},{%0,%1,%2,%3};"
        : "+f"(d[0]), "+f"(d[1]), "+f"(d[2]), "+f"(d[3])
        : "r"(a0), "r"(a1), "r"(a2), "r"(a3), "r"(b0), "r"(b1));
}

__device__ __forceinline__ void ldm4(unsigned &r0, unsigned &r1, unsigned &r2, unsigned &r3,
                                     unsigned addr) {
    asm volatile("ldmatrix.sync.aligned.m8n8.x4.shared.b16 {%0,%1,%2,%3}, [%4];"
                 : "=r"(r0), "=r"(r1), "=r"(r2), "=r"(r3) : "r"(addr));
}

__device__ __forceinline__ void cpa16(__nv_bfloat16* dst, const __nv_bfloat16* src) {
    unsigned a = (unsigned)__cvta_generic_to_shared(dst);
    asm volatile("cp.async.cg.shared.global [%0], [%1], 16;" :: "r"(a), "l"(src));
}
#define CPA_COMMIT() asm volatile("cp.async.commit_group;")
#define CPA_WAIT0()  asm volatile("cp.async.wait_group 0;")

// ------------------------- prep kernels -------------------------
__global__ void pack_plane(const float* __restrict__ src,
                           __nv_bfloat16* __restrict__ hi, __nv_bfloat16* __restrict__ lo,
                           int n4)
{
    int i = blockIdx.x * blockDim.x + threadIdx.x;
    if (i < n4) {
        float4 v = ((const float4*)src)[i];
        __nv_bfloat16 h0 = __float2bfloat16(v.x);
        __nv_bfloat16 h1 = __float2bfloat16(v.y);
        __nv_bfloat16 h2 = __float2bfloat16(v.z);
        __nv_bfloat16 h3 = __float2bfloat16(v.w);
        __nv_bfloat162 hh0; hh0.x = h0; hh0.y = h1;
        __nv_bfloat162 hh1; hh1.x = h2; hh1.y = h3;
        __nv_bfloat162 ll0;
        ll0.x = __float2bfloat16(v.x - __bfloat162float(h0));
        ll0.y = __float2bfloat16(v.y - __bfloat162float(h1));
        __nv_bfloat162 ll1;
        ll1.x = __float2bfloat16(v.z - __bfloat162float(h2));
        ll1.y = __float2bfloat16(v.w - __bfloat162float(h3));
        ((__nv_bfloat162*)hi)[i * 2]     = hh0;
        ((__nv_bfloat162*)hi)[i * 2 + 1] = hh1;
        ((__nv_bfloat162*)lo)[i * 2]     = ll0;
        ((__nv_bfloat162*)lo)[i * 2 + 1] = ll1;
    }
}

__global__ void pack_wT(const float* __restrict__ W,
                        __nv_bfloat16* __restrict__ hi, __nv_bfloat16* __restrict__ lo,
                        int K, int N)
{
    __shared__ float t[32][33];
    const int n0 = blockIdx.x * 32, k0 = blockIdx.y * 32;
    const int tx = threadIdx.x, ty = threadIdx.y;
    #pragma unroll
    for (int r = 0; r < 32; r += 8)
        t[ty + r][tx] = W[(size_t)(k0 + ty + r) * N + n0 + tx];
    __syncthreads();
    #pragma unroll
    for (int r = 0; r < 32; r += 8) {
        float v = t[tx][ty + r];
        size_t o = (size_t)(n0 + ty + r) * K + k0 + tx;
        __nv_bfloat16 h = __float2bfloat16(v);
        hi[o] = h;
        lo[o] = __float2bfloat16(v - __bfloat162float(h));
    }
}

__global__ void code_norm_kernel(const float* __restrict__ cb) {
    int c = blockIdx.x * blockDim.x + threadIdx.x;
    if (c < NCODES) {
        float s = 0.f;
        #pragma unroll 4
        for (int d = 0; d < EMBED; d++) {
            float v = cb[c * EMBED + d];
            s = fmaf(v, v, s);
        }
        g_cnorm[c] = s;
    }
}

__global__ void zero_loss_kernel() { g_loss = 0.0; }

// =========================================================================
// bf16 3-term GEMM with ldmatrix fragment loads.
// =========================================================================
#define GAS 5120   // 128*40 bf16 per plane buffer
#define GEMM_SMEM (8 * GAS * 2)   // 81920 bytes

template <int ACT, int SPLIT>
__global__ __launch_bounds__(256, 1)
void gemm_bf(const __nv_bfloat16* __restrict__ Ah, const __nv_bfloat16* __restrict__ Al,
             const __nv_bfloat16* __restrict__ Wh, const __nv_bfloat16* __restrict__ Wl,
             const float* __restrict__ bias,
             float* __restrict__ C,
             __nv_bfloat16* __restrict__ Ch, __nv_bfloat16* __restrict__ Cl,
             int M, int K, int N)
{
    extern __shared__ __align__(16) char smraw[];
    __nv_bfloat16* sm  = (__nv_bfloat16*)smraw;
    __nv_bfloat16* AsH = sm;               // [2][GAS]
    __nv_bfloat16* AsL = sm + 2 * GAS;
    __nv_bfloat16* WsH = sm + 4 * GAS;
    __nv_bfloat16* WsL = sm + 6 * GAS;
    const unsigned smu = (unsigned)__cvta_generic_to_shared(sm);

    const int tid  = threadIdx.x;
    const int m0   = blockIdx.y * 128;
    const int n0   = blockIdx.x * 128;
    const int warp = tid >> 5, lane = tid & 31;
    const int mw = (warp & 1) * 64;
    const int nw = (warp >> 1) * 32;
    const int g  = lane >> 2;
    const int tq = lane & 3;

    // ldmatrix lane mappings
    const int lmr = lane & 15, lmk = (lane >> 4) * 8;                 // A x4
    const int brow = ((lane >> 4) << 3) + (lane & 7);                 // B x4 (j pair)
    const int bk8  = ((lane >> 3) & 1) << 3;

    // staging mapping
    const int srow = tid >> 2;
    const int sfq  = (tid & 3) * 8;
    const size_t aoff = (size_t)(m0 + srow) * K + sfq;
    const size_t woff = (size_t)(n0 + srow) * K + sfq;
    const int s_lo = srow * 40 + sfq;
    const int s_hi = (srow + 64) * 40 + sfq;

    float acc[4][4][4] = {};

    float4 ah0 = *(const float4*)(Ah + aoff);
    float4 ah1 = *(const float4*)(Ah + aoff + (size_t)64 * K);
    float4 al0 = *(const float4*)(Al + aoff);
    float4 al1 = *(const float4*)(Al + aoff + (size_t)64 * K);
    float4 wh0 = *(const float4*)(Wh + woff);
    float4 wh1 = *(const float4*)(Wh + woff + (size_t)64 * K);
    float4 wl0 = *(const float4*)(Wl + woff);
    float4 wl1 = *(const float4*)(Wl + woff + (size_t)64 * K);
    *(float4*)&AsH[s_lo] = ah0;  *(float4*)&AsH[s_hi] = ah1;
    *(float4*)&AsL[s_lo] = al0;  *(float4*)&AsL[s_hi] = al1;
    *(float4*)&WsH[s_lo] = wh0;  *(float4*)&WsH[s_hi] = wh1;
    *(float4*)&WsL[s_lo] = wl0;  *(float4*)&WsL[s_hi] = wl1;
    __syncthreads();

    const int KT = K >> 5;
    for (int kt = 0; kt < KT; kt++) {
        const int cur = kt & 1, nxt = cur ^ 1;
        if (kt + 1 < KT) {
            const size_t ao = aoff + (kt + 1) * 32;
            const size_t wo = woff + (kt + 1) * 32;
            ah0 = *(const float4*)(Ah + ao);
            ah1 = *(const float4*)(Ah + ao + (size_t)64 * K);
            al0 = *(const float4*)(Al + ao);
            al1 = *(const float4*)(Al + ao + (size_t)64 * K);
            wh0 = *(const float4*)(Wh + wo);
            wh1 = *(const float4*)(Wh + wo + (size_t)64 * K);
            wl0 = *(const float4*)(Wl + wo);
            wl1 = *(const float4*)(Wl + wo + (size_t)64 * K);
        }
        // byte base of each plane's current buffer
        const unsigned aHb = smu + (unsigned)(cur * GAS) * 2;
        const unsigned aLb = smu + (unsigned)((2 + cur) * GAS) * 2;
        const unsigned wHb = smu + (unsigned)((4 + cur) * GAS) * 2;
        const unsigned wLb = smu + (unsigned)((6 + cur) * GAS) * 2;
        #pragma unroll
        for (int ks = 0; ks < 32; ks += 16) {
            unsigned ahr[4][4], alr[4][4];
            #pragma unroll
            for (int i = 0; i < 4; i++) {
                const unsigned eo = (unsigned)((mw + i * 16 + lmr) * 40 + ks + lmk) * 2;
                ldm4(ahr[i][0], ahr[i][1], ahr[i][2], ahr[i][3], aHb + eo);
                ldm4(alr[i][0], alr[i][1], alr[i][2], alr[i][3], aLb + eo);
            }
            unsigned bhr[4][2], blr[4][2];
            #pragma unroll
            for (int jp = 0; jp < 2; jp++) {
                const unsigned eo = (unsigned)((nw + jp * 16 + brow) * 40 + ks + bk8) * 2;
                ldm4(bhr[jp*2][0], bhr[jp*2][1], bhr[jp*2+1][0], bhr[jp*2+1][1], wHb + eo);
                ldm4(blr[jp*2][0], blr[jp*2][1], blr[jp*2+1][0], blr[jp*2+1][1], wLb + eo);
            }
            #pragma unroll
            for (int i = 0; i < 4; i++)
                #pragma unroll
                for (int j = 0; j < 4; j++) {
                    mma16(acc[i][j], ahr[i][0], ahr[i][1], ahr[i][2], ahr[i][3], bhr[j][0], bhr[j][1]);
                    mma16(acc[i][j], ahr[i][0], ahr[i][1], ahr[i][2], ahr[i][3], blr[j][0], blr[j][1]);
                    mma16(acc[i][j], alr[i][0], alr[i][1], alr[i][2], alr[i][3], bhr[j][0], bhr[j][1]);
                }
        }
        if (kt + 1 < KT) {
            *(float4*)&AsH[nxt * GAS + s_lo] = ah0;  *(float4*)&AsH[nxt * GAS + s_hi] = ah1;
            *(float4*)&AsL[nxt * GAS + s_lo] = al0;  *(float4*)&AsL[nxt * GAS + s_hi] = al1;
            *(float4*)&WsH[nxt * GAS + s_lo] = wh0;  *(float4*)&WsH[nxt * GAS + s_hi] = wh1;
            *(float4*)&WsL[nxt * GAS + s_lo] = wl0;  *(float4*)&WsL[nxt * GAS + s_hi] = wl1;
            __syncthreads();
        }
    }

    // epilogue
    #pragma unroll
    for (int j = 0; j < 4; j++) {
        const int col = n0 + nw + j * 8 + tq * 2;
        const float b0 = bias[col], b1 = bias[col + 1];
        #pragma unroll
        for (int i = 0; i < 4; i++) {
            const int r = m0 + mw + i * 16 + g;
            float v0 = acc[i][j][0] + b0;
            float v1 = acc[i][j][1] + b1;
            float v2 = acc[i][j][2] + b0;
            float v3 = acc[i][j][3] + b1;
            if (ACT) { v0 = gelu_exact(v0); v1 = gelu_exact(v1); v2 = gelu_exact(v2); v3 = gelu_exact(v3); }
            const size_t o0 = (size_t)r * N + col;
            const size_t o1 = (size_t)(r + 8) * N + col;
            if (SPLIT) {
                __nv_bfloat16 h0 = __float2bfloat16(v0), h1 = __float2bfloat16(v1);
                __nv_bfloat16 h2 = __float2bfloat16(v2), h3 = __float2bfloat16(v3);
                __nv_bfloat162 hh0; hh0.x = h0; hh0.y = h1;
                __nv_bfloat162 hh1; hh1.x = h2; hh1.y = h3;
                __nv_bfloat162 ll0;
                ll0.x = __float2bfloat16(v0 - __bfloat162float(h0));
                ll0.y = __float2bfloat16(v1 - __bfloat162float(h1));
                __nv_bfloat162 ll1;
                ll1.x = __float2bfloat16(v2 - __bfloat162float(h2));
                ll1.y = __float2bfloat16(v3 - __bfloat162float(h3));
                *(__nv_bfloat162*)&Ch[o0] = hh0;
                *(__nv_bfloat162*)&Ch[o1] = hh1;
                *(__nv_bfloat162*)&Cl[o0] = ll0;
                *(__nv_bfloat162*)&Cl[o1] = ll1;
            } else {
                *(float2*)&C[o0] = make_float2(v0, v1);
                *(float2*)&C[o1] = make_float2(v2, v3);
            }
        }
    }
}

// =========================================================================
// VQ with ldmatrix fragment loads.
// =========================================================================
#define ZPS 17408            // 128*136
#define VQ_SMEM (((size_t)6 * ZPS) * 2 + NCODES * 4)

__global__ __launch_bounds__(256, 1)
void vq_kernel(const __nv_bfloat16* __restrict__ zh, const __nv_bfloat16* __restrict__ zl,
               const __nv_bfloat16* __restrict__ cbh, const __nv_bfloat16* __restrict__ cbl,
               const float* __restrict__ cb,
               __nv_bfloat16* __restrict__ qh, __nv_bfloat16* __restrict__ ql)
{
    extern __shared__ __align__(16) char smraw[];
    __nv_bfloat16* sm  = (__nv_bfloat16*)smraw;
    __nv_bfloat16* ZsH = sm;
    __nv_bfloat16* ZsL = sm + ZPS;
    __nv_bfloat16* Cb  = sm + 2 * ZPS;
    float* cn = (float*)(sm + 6 * ZPS);
    const unsigned smu = (unsigned)__cvta_generic_to_shared(sm);

    __shared__ float red_d[128][4];
    __shared__ int   red_i[128][4];
    __shared__ int   best_idx[128];
    __shared__ float warp_sum[8];

    const int tid = threadIdx.x;
    const int t0  = blockIdx.x * 128;
    const int warp = tid >> 5, lane = tid & 31;
    const int mw = (warp & 1) * 64;
    const int nw = (warp >> 1) * 32;
    const int g  = lane >> 2;
    const int tq = lane & 3;

    const int lmr = lane & 15, lmk = (lane >> 4) * 8;
    const int brow = ((lane >> 4) << 3) + (lane & 7);
    const int bk8  = ((lane >> 3) & 1) << 3;

    *(float4*)&cn[tid * 4] = *(const float4*)&g_cnorm[tid * 4];

    #pragma unroll
    for (int l = 0; l < 8; l++) {
        int idx = l * 256 + tid;
        int row = idx >> 4, c16 = (idx & 15) * 8;
        cpa16(ZsH + row * 136 + c16, zh + (size_t)(t0 + row) * EMBED + c16);
        cpa16(ZsL + row * 136 + c16, zl + (size_t)(t0 + row) * EMBED + c16);
        cpa16(Cb + row * 136 + c16,        cbh + (size_t)row * EMBED + c16);
        cpa16(Cb + ZPS + row * 136 + c16,  cbl + (size_t)row * EMBED + c16);
    }
    CPA_COMMIT();
    CPA_WAIT0();
    __syncthreads();

    float bestD[8];
    int   bestI[8];
    #pragma unroll
    for (int s = 0; s < 8; s++) { bestD[s] = 3.4e38f; bestI[s] = 0; }

    for (int ct = 0; ct < 8; ct++) {
        const int cur = ct & 1, nxt = cur ^ 1;
        const unsigned cHb = smu + (unsigned)(2 * ZPS + cur * 2 * ZPS) * 2;
        const unsigned cLb = cHb + (unsigned)ZPS * 2;

        if (ct < 7) {
            const int c0n = (ct + 1) * 128;
            __nv_bfloat16* dH = Cb + nxt * 2 * ZPS;
            __nv_bfloat16* dL = dH + ZPS;
            #pragma unroll
            for (int l = 0; l < 8; l++) {
                int idx = l * 256 + tid;
                int row = idx >> 4, c16 = (idx & 15) * 8;
                cpa16(dH + row * 136 + c16, cbh + (size_t)(c0n + row) * EMBED + c16);
                cpa16(dL + row * 136 + c16, cbl + (size_t)(c0n + row) * EMBED + c16);
            }
            CPA_COMMIT();
        }

        float acc[4][4][4] = {};
        #pragma unroll
        for (int kt = 0; kt < 8; kt++) {
            const int kb = kt * 16;
            unsigned ahr[4][4], alr[4][4];
            #pragma unroll
            for (int i = 0; i < 4; i++) {
                const unsigned eo = (unsigned)((mw + i * 16 + lmr) * 136 + kb + lmk) * 2;
                ldm4(ahr[i][0], ahr[i][1], ahr[i][2], ahr[i][3], smu + eo);
                ldm4(alr[i][0], alr[i][1], alr[i][2], alr[i][3], smu + (unsigned)ZPS * 2 + eo);
            }
            unsigned bhr[4][2], blr[4][2];
            #pragma unroll
            for (int jp = 0; jp < 2; jp++) {
                const unsigned eo = (unsigned)((nw + jp * 16 + brow) * 136 + kb + bk8) * 2;
                ldm4(bhr[jp*2][0], bhr[jp*2][1], bhr[jp*2+1][0], bhr[jp*2+1][1], cHb + eo);
                ldm4(blr[jp*2][0], blr[jp*2][1], blr[jp*2+1][0], blr[jp*2+1][1], cLb + eo);
            }
            #pragma unroll
            for (int i = 0; i < 4; i++)
                #pragma unroll
                for (int j = 0; j < 4; j++) {
                    mma16(acc[i][j], ahr[i][0], ahr[i][1], ahr[i][2], ahr[i][3], bhr[j][0], bhr[j][1]);
                    mma16(acc[i][j], ahr[i][0], ahr[i][1], ahr[i][2], ahr[i][3], blr[j][0], blr[j][1]);
                    mma16(acc[i][j], alr[i][0], alr[i][1], alr[i][2], alr[i][3], bhr[j][0], bhr[j][1]);
                }
        }

        const int c0 = ct * 128;
        #pragma unroll
        for (int j = 0; j < 4; j++) {
            const int cbase = c0 + nw + j * 8 + tq * 2;
            const float cn0 = cn[cbase], cn1 = cn[cbase + 1];
            #pragma unroll
            for (int i = 0; i < 4; i++) {
                #pragma unroll
                for (int h = 0; h < 2; h++) {
                    const int s = i * 2 + h;
                    float d0 = fmaf(-2.0f, acc[i][j][h * 2 + 0], cn0);
                    float d1 = fmaf(-2.0f, acc[i][j][h * 2 + 1], cn1);
                    if (d0 < bestD[s] || (d0 == bestD[s] && cbase < bestI[s])) { bestD[s] = d0; bestI[s] = cbase; }
                    if (d1 < bestD[s] || (d1 == bestD[s] && cbase + 1 < bestI[s])) { bestD[s] = d1; bestI[s] = cbase + 1; }
                }
            }
        }

        if (ct < 7) {
            CPA_WAIT0();
            __syncthreads();
        }
    }

    #pragma unroll
    for (int s = 0; s < 8; s++) {
        #pragma unroll
        for (int o = 1; o < 4; o <<= 1) {
            float od = __shfl_xor_sync(0xFFFFFFFFu, bestD[s], o);
            int   oi = __shfl_xor_sync(0xFFFFFFFFu, bestI[s], o);
            if (od < bestD[s] || (od == bestD[s] && oi < bestI[s])) { bestD[s] = od; bestI[s] = oi; }
        }
    }
    if (tq == 0) {
        #pragma unroll
        for (int s = 0; s < 8; s++) {
            const int row = mw + (s >> 1) * 16 + (s & 1) * 8 + g;
            red_d[row][warp >> 1] = bestD[s];
            red_i[row][warp >> 1] = bestI[s];
        }
    }
    __syncthreads();
    if (tid < 128) {
        float bd = red_d[tid][0];
        int   bi = red_i[tid][0];
        #pragma unroll
        for (int x = 1; x < 4; x++) {
            float d = red_d[tid][x];
            int   c = red_i[tid][x];
            if (d < bd || (d == bd && c < bi)) { bd = d; bi = c; }
        }
        best_idx[tid] = bi;
        g_idx[t0 + tid] = bi;
    }
    __syncthreads();

    float lsum = 0.f;
    #pragma unroll 4
    for (int l = 0; l < 64; l++) {
        int e = l * 256 + tid;
        int trow = e >> 7;
        int d    = e & 127;
        int c    = best_idx[trow];
        float zv = __bfloat162float(ZsH[trow * 136 + d]) + __bfloat162float(ZsL[trow * 136 + d]);
        float diff = cb[(size_t)c * EMBED + d] - zv;
        float qv = zv + diff;
        __nv_bfloat16 hh = __float2bfloat16(qv);
        size_t go = (size_t)t0 * EMBED + e;
        qh[go] = hh;
        ql[go] = __float2bfloat16(qv - __bfloat162float(hh));
        lsum = fmaf(diff, diff, lsum);
    }
    #pragma unroll
    for (int o = 16; o > 0; o >>= 1) lsum += __shfl_down_sync(0xFFFFFFFFu, lsum, o);
    if (lane == 0) warp_sum[warp] = lsum;
    __syncthreads();
    if (tid == 0) {
        float s = 0.f;
        #pragma unroll
        for (int w = 0; w < 8; w++) s += warp_sum[w];
        atomicAdd(&g_loss, (double)s);
    }
}

// ------------------------- tail outputs -------------------------
__global__ void finalize_kernel(float* __restrict__ out)
{
    int i = blockIdx.x * 256 + threadIdx.x;
    if (i < NTOKENS_TOTAL) out[REC_ELEMS + i] = (float)g_idx[i];
    if (i == 0) out[REC_ELEMS + NTOKENS_TOTAL] = (float)(g_loss / (double)QELEMS);
}

// ------------------------- launch -------------------------
extern "C" void kernel_launch(void* const* d_in, const int* in_sizes, int n_in,
                              void* d_out, int out_size)
{
    const float* x   = (const float*)d_in[0];
    const float* eW1 = (const float*)d_in[1];
    const float* eb1 = (const float*)d_in[2];
    const float* eW2 = (const float*)d_in[3];
    const float* eb2 = (const float*)d_in[4];
    const float* eW3 = (const float*)d_in[5];
    const float* eb3 = (const float*)d_in[6];
    const float* dW1 = (const float*)d_in[7];
    const float* db1 = (const float*)d_in[8];
    const float* dW2 = (const float*)d_in[9];
    const float* db2 = (const float*)d_in[10];
    const float* dW3 = (const float*)d_in[11];
    const float* db3 = (const float*)d_in[12];
    const float* cb  = (const float*)d_in[13];
    float* out = (float*)d_out;

    __nv_bfloat16 *xh, *xl, *h1h, *h1l, *h2h, *h2l, *zh, *zl, *qh, *ql;
    __nv_bfloat16 *h3h, *h3l, *h4h, *h4l, *wh, *wl;
    cudaGetSymbolAddress((void**)&xh,  g_xh);
    cudaGetSymbolAddress((void**)&xl,  g_xl);
    cudaGetSymbolAddress((void**)&h1h, g_h1h);
    cudaGetSymbolAddress((void**)&h1l, g_h1l);
    cudaGetSymbolAddress((void**)&h2h, g_h2h);
    cudaGetSymbolAddress((void**)&h2l, g_h2l);
    cudaGetSymbolAddress((void**)&zh,  g_zh);
    cudaGetSymbolAddress((void**)&zl,  g_zl);
    cudaGetSymbolAddress((void**)&qh,  g_qh);
    cudaGetSymbolAddress((void**)&ql,  g_ql);
    cudaGetSymbolAddress((void**)&h3h, g_h3h);
    cudaGetSymbolAddress((void**)&h3l, g_h3l);
    cudaGetSymbolAddress((void**)&h4h, g_h4h);
    cudaGetSymbolAddress((void**)&h4l, g_h4l);
    cudaGetSymbolAddress((void**)&wh,  g_wh);
    cudaGetSymbolAddress((void**)&wl,  g_wl);

    cudaFuncSetAttribute(gemm_bf<1, 1>, cudaFuncAttributeMaxDynamicSharedMemorySize, GEMM_SMEM);
    cudaFuncSetAttribute(gemm_bf<0, 1>, cudaFuncAttributeMaxDynamicSharedMemorySize, GEMM_SMEM);
    cudaFuncSetAttribute(gemm_bf<0, 0>, cudaFuncAttributeMaxDynamicSharedMemorySize, GEMM_SMEM);
    cudaFuncSetAttribute(vq_kernel, cudaFuncAttributeMaxDynamicSharedMemorySize, (int)VQ_SMEM);

    zero_loss_kernel<<<1, 1>>>();
    code_norm_kernel<<<4, 256>>>(cb);

    pack_plane<<<(NB * IN_DIM / 4 + 255) / 256, 256>>>(x,  xh, xl, NB * IN_DIM / 4);
    pack_plane<<<(NCODES * EMBED / 4 + 255) / 256, 256>>>(cb, wh + OFF_CB, wl + OFF_CB, NCODES * EMBED / 4);
    dim3 tb(32, 8);
    pack_wT<<<dim3(HID / 32,    IN_DIM / 32), tb>>>(eW1, wh + OFF_EW1, wl + OFF_EW1, IN_DIM, HID);
    pack_wT<<<dim3(HID / 32,    HID / 32),    tb>>>(eW2, wh + OFF_EW2, wl + OFF_EW2, HID,    HID);
    pack_wT<<<dim3(LATENT / 32, HID / 32),    tb>>>(eW3, wh + OFF_EW3, wl + OFF_EW3, HID,    LATENT);
    pack_wT<<<dim3(HID / 32,    LATENT / 32), tb>>>(dW1, wh + OFF_DW1, wl + OFF_DW1, LATENT, HID);
    pack_wT<<<dim3(HID / 32,    HID / 32),    tb>>>(dW2, wh + OFF_DW2, wl + OFF_DW2, HID,    HID);
    pack_wT<<<dim3(IN_DIM / 32, HID / 32),    tb>>>(dW3, wh + OFF_DW3, wl + OFF_DW3, HID,    IN_DIM);

    gemm_bf<1, 1><<<dim3(HID / 128,    NB / 128), 256, GEMM_SMEM>>>(
        xh, xl, wh + OFF_EW1, wl + OFF_EW1, eb1, nullptr, h1h, h1l, NB, IN_DIM, HID);
    gemm_bf<1, 1><<<dim3(HID / 128,    NB / 128), 256, GEMM_SMEM>>>(
        h1h, h1l, wh + OFF_EW2, wl + OFF_EW2, eb2, nullptr, h2h, h2l, NB, HID, HID);
    gemm_bf<0, 1><<<dim3(LATENT / 128, NB / 128), 256, GEMM_SMEM>>>(
        h2h, h2l, wh + OFF_EW3, wl + OFF_EW3, eb3, nullptr, zh, zl, NB, HID, LATENT);

    vq_kernel<<<NTOKENS_TOTAL / 128, 256, VQ_SMEM>>>(
        zh, zl, wh + OFF_CB, wl + OFF_CB, cb, qh, ql);

    gemm_bf<1, 1><<<dim3(HID / 128,    NB / 128), 256, GEMM_SMEM>>>(
        qh, ql, wh + OFF_DW1, wl + OFF_DW1, db1, nullptr, h3h, h3l, NB, LATENT, HID);
    gemm_bf<1, 1><<<dim3(HID / 128,    NB / 128), 256, GEMM_SMEM>>>(
        h3h, h3l, wh + OFF_DW2, wl + OFF_DW2, db2, nullptr, h4h, h4l, NB, HID, HID);
    gemm_bf<0, 0><<<dim3(IN_DIM / 128, NB / 128), 256, GEMM_SMEM>>>(
        h4h, h4l, wh + OFF_DW3, wl + OFF_DW3, db3, out, nullptr, nullptr, NB, HID, IN_DIM);

    if (out_size >= REC_ELEMS + NTOKENS_TOTAL + 1)
        finalize_kernel<<<(NTOKENS_TOTAL + 255) / 256, 256>>>(out);
}